// round 13
// baseline (speedup 1.0000x reference)
#include <cuda_runtime.h>
#include <cuda_fp16.h>
#include <cstdint>
#include <math.h>

// Problem constants (R=1024, S=128, J=24, H=64, multires=6)
constexpr int NPTS = 1024 * 128;
constexpr int NJ   = 24;
constexpr int NH   = 64;
constexpr int NI   = 39;
constexpr int NPH  = 12;     // phases: 2 joints each
constexpr int KP   = 80;     // K per phase: 39 + 1 pad + 39 + 1 pad
constexpr int ASTR = 176;    // A row stride bytes (80 cols * 2B = 160, pad to 176)
constexpr int BSTR = 144;    // B row stride bytes (64 cols * 2B = 128, pad to 144)

// ---- dynamic SMEM layout ----
constexpr int SM_A   = 0;                       // A fp16: 128 x 176 = 22528
constexpr int SM_B0  = 22528;                   // 80 x 144 = 11520
constexpr int SM_B1  = 34048;
constexpr int SM_TR  = 45568;                   // 24x16 f32 = 1536
constexpr int SM_SZ  = 47104;                   // 4 CTAs/SM = 188KB
// epilogue overlays: H[128 x 65 f32] at 0 (33280B <= 34048), W1 at SM_B1

// relu(h) row-major [NPTS, NJ]; warp_kernel reads the faithful view(J,-1).T
// scramble as linear index j*NPTS + m.
__device__ float g_h[(size_t)NPTS * NJ];
// fp16 B images per phase: [80 k][72 n-stride] (byte image of the smem tile)
__device__ __align__(16) unsigned short g_Bh[NPH * KP * 72];

// ---------------- helpers ----------------
__device__ __forceinline__ uint32_t smem_u32(const void* p) {
    uint32_t a;
    asm("{ .reg .u64 t; cvta.to.shared.u64 t, %1; cvt.u32.u64 %0, t; }" : "=r"(a) : "l"(p));
    return a;
}
__device__ __forceinline__ void ldsm4(uint32_t* r, uint32_t addr) {
    asm volatile("ldmatrix.sync.aligned.m8n8.x4.shared.b16 {%0,%1,%2,%3}, [%4];"
                 : "=r"(r[0]), "=r"(r[1]), "=r"(r[2]), "=r"(r[3]) : "r"(addr));
}
__device__ __forceinline__ void ldsm4t(uint32_t* r, uint32_t addr) {
    asm volatile("ldmatrix.sync.aligned.m8n8.x4.trans.shared.b16 {%0,%1,%2,%3}, [%4];"
                 : "=r"(r[0]), "=r"(r[1]), "=r"(r[2]), "=r"(r[3]) : "r"(addr));
}
__device__ __forceinline__ void mma16816h(float* d, const uint32_t* a,
                                          uint32_t b0, uint32_t b1) {
    asm volatile(
        "mma.sync.aligned.m16n8k16.row.col.f32.f16.f16.f32 "
        "{%0,%1,%2,%3}, {%4,%5,%6,%7}, {%8,%9}, {%0,%1,%2,%3};"
        : "+f"(d[0]), "+f"(d[1]), "+f"(d[2]), "+f"(d[3])
        : "r"(a[0]), "r"(a[1]), "r"(a[2]), "r"(a[3]), "r"(b0), "r"(b1));
}
// pack two f32 -> f16x2 (a in low half)
__device__ __forceinline__ uint32_t packh2(float a, float b) {
    uint32_t r;
    asm("cvt.rn.f16x2.f32 %0, %1, %2;" : "=r"(r) : "f"(b), "f"(a));
    return r;
}
__device__ __forceinline__ void sts128(uint32_t addr, uint32_t a, uint32_t b,
                                       uint32_t c, uint32_t d) {
    asm volatile("st.shared.v4.b32 [%0], {%1,%2,%3,%4};"
                 :: "r"(addr), "r"(a), "r"(b), "r"(c), "r"(d) : "memory");
}

// ---------------------------------------------------------------------------
// Prep: per-phase B tiles: k rows 0..38 = joint 2p, 39 zero, 40..78 = joint
// 2p+1, 79 zero.  B[k][n] = fp16(w0[(j*39+k)*64 + n]); pad cols zeroed.
// ---------------------------------------------------------------------------
__global__ void prep_b(const float* __restrict__ w0) {
    int idx = blockIdx.x * 256 + threadIdx.x;
    if (idx >= NPH * KP * 72) return;
    int p = idx / (KP * 72), rem = idx % (KP * 72);
    int kk = rem / 72, n = rem % 72;
    float v = 0.f;
    if (n < NH) {
        if (kk < NI)                  v = w0[((2 * p)     * NI + kk)        * NH + n];
        else if (kk >= 40 && kk < 79) v = w0[((2 * p + 1) * NI + (kk - 40)) * NH + n];
    }
    g_Bh[p * (KP * 72) + kk * 72 + n] = __half_as_ushort(__float2half_rn(v));
}

// ---------------------------------------------------------------------------
// Kernel 1: 128-pt tile, 256 threads (8 warps), 4 CTAs/SM target.
// Feature work: thread (pt, half) computes joint 2p+half of point pt; packs
// are streamed to SMEM through a rolling 4-reg window (low register count).
// GEMM: single-pass fp16 D = Ah*Bh.  Warp w: rows (w&3)*32, cols (w>>2)*32.
// ---------------------------------------------------------------------------
__global__ __launch_bounds__(256, 4)
void weights_mma(const float* __restrict__ xyz,
                 const float* __restrict__ transforms,
                 const float* __restrict__ w1)
{
    extern __shared__ __align__(16) char sm[];
    const uint32_t sb = smem_u32(sm);
    const int tid = threadIdx.x, lane = tid & 31, w = tid >> 5;
    const int pt = tid & 127, half = tid >> 7;
    const int wr = w & 3, wc = w >> 2;
    const int n = blockIdx.x * 128 + pt;
    const int oct = lane >> 3, oi = lane & 7;

    for (int i = tid; i < NJ * 16; i += 256)
        ((float*)(sm + SM_TR))[i] = transforms[i];
    __syncthreads();

    const float x = xyz[3 * n + 0];
    const float y = xyz[3 * n + 1];
    const float z = xyz[3 * n + 2];

    float acc[2][4][4];
#pragma unroll
    for (int a = 0; a < 2; ++a)
#pragma unroll
        for (int b = 0; b < 4; ++b)
#pragma unroll
            for (int c = 0; c < 4; ++c) acc[a][b][c] = 0.f;

    for (int p = 0; p < NPH; ++p) {
        const int bB = (p & 1) ? SM_B1 : SM_B0;

        // stage this phase's B tile: 80 rows x 144B = 720 uint4 (FULL tile)
        {
            const uint4* shp = (const uint4*)(g_Bh + p * (KP * 72));
            uint4* dh = (uint4*)(sm + bB);
            for (int i = tid; i < 720; i += 256) dh[i] = shp[i];
        }

        __syncthreads();   // all warps done reading A of phase p-1

        // features for joint (2p + half), streamed to A via 4-pack window
        {
            const int j = 2 * p + half;
            const float* T = (const float*)(sm + SM_TR) + j * 16;
            float lx = fmaf(T[0], x, fmaf(T[1], y, fmaf(T[2],  z, T[3])));
            float ly = fmaf(T[4], x, fmaf(T[5], y, fmaf(T[6],  z, T[7])));
            float lz = fmaf(T[8], x, fmaf(T[9], y, fmaf(T[10], z, T[11])));
            const float INV = 2.0f / 3.0f;
            lx = (lx + 1.5f) * INV - 1.0f;
            ly = (ly + 1.5f) * INV - 1.0f;
            lz = (lz + 1.5f) * INV - 1.0f;

            const uint32_t abase = sb + SM_A + pt * ASTR + half * 80;
            uint32_t q[4];
            int qi = 0, chunk = 0;
            auto push = [&](uint32_t v) {
                q[qi++] = v;
                if (qi == 4) {
                    sts128(abase + chunk * 16, q[0], q[1], q[2], q[3]);
                    qi = 0; ++chunk;
                }
            };

            push(packh2(lx, ly));
            float carry = lz;
            float sx, cx, sy, cy, sz, cz;
            __sincosf(lx, &sx, &cx);
            __sincosf(ly, &sy, &cy);
            __sincosf(lz, &sz, &cz);
#pragma unroll
            for (int ff = 0; ff < 6; ++ff) {
                push(packh2(carry, sx));
                push(packh2(sy, sz));
                push(packh2(cx, cy));
                carry = cz;
                if (ff < 5) {
                    // sin(2a) = 2 s c ; cos(2a) = 1 - 2 s^2
                    float nsx = 2.f * sx * cx, ncx = fmaf(-2.f * sx, sx, 1.f);
                    float nsy = 2.f * sy * cy, ncy = fmaf(-2.f * sy, sy, 1.f);
                    float nsz = 2.f * sz * cz, ncz = fmaf(-2.f * sz, sz, 1.f);
                    sx = nsx; cx = ncx; sy = nsy; cy = ncy; sz = nsz; cz = ncz;
                }
            }
            push(packh2(carry, 0.f));   // cz5 + pad column -> flushes chunk 4
        }
        __syncthreads();   // A + B staged

        // ldmatrix + mma: warp computes rows [wr*32,+32) x cols [wc*32,+32)
#pragma unroll
        for (int ks = 0; ks < 5; ++ks) {
            uint32_t ah[2][4];
#pragma unroll
            for (int mt = 0; mt < 2; ++mt) {
                uint32_t ra = (uint32_t)((wr * 32 + mt * 16 + (oct & 1) * 8 + oi) * ASTR
                                         + ks * 32 + (oct >> 1) * 16);
                ldsm4(ah[mt], sb + SM_A + ra);
            }
#pragma unroll
            for (int np = 0; np < 2; ++np) {
                uint32_t rb = (uint32_t)((ks * 16 + (oct & 1) * 8 + oi) * BSTR
                                         + wc * 64 + np * 32 + (oct >> 1) * 16);
                uint32_t bh[4];
                ldsm4t(bh, sb + bB + rb);
#pragma unroll
                for (int mt = 0; mt < 2; ++mt) {
                    mma16816h(acc[mt][2 * np + 0], ah[mt], bh[0], bh[1]);
                    mma16816h(acc[mt][2 * np + 1], ah[mt], bh[2], bh[3]);
                }
            }
        }
    }
    __syncthreads();   // all warps done with A/B regions

    // Epilogue: relu(acc) -> H smem [128 x 64], stride 65 f32 (overlays A/B0)
    float* hs = (float*)(sm + 0);
#pragma unroll
    for (int mt = 0; mt < 2; ++mt) {
        const int rr = wr * 32 + mt * 16 + (lane >> 2);
#pragma unroll
        for (int nt = 0; nt < 4; ++nt) {
            const int cc = wc * 32 + nt * 8 + (lane & 3) * 2;
            hs[rr * 65 + cc]           = fmaxf(acc[mt][nt][0], 0.f);
            hs[rr * 65 + cc + 1]       = fmaxf(acc[mt][nt][1], 0.f);
            hs[(rr + 8) * 65 + cc]     = fmaxf(acc[mt][nt][2], 0.f);
            hs[(rr + 8) * 65 + cc + 1] = fmaxf(acc[mt][nt][3], 0.f);
        }
    }
    for (int i = tid; i < (NH * NJ) / 4; i += 256)
        ((float4*)(sm + SM_B1))[i] = ((const float4*)w1)[i];
    __syncthreads();

    // Layer 2 + relu: thread (pt, half) does row pt, jj in [half*12, half*12+12)
    const float* myrow = hs + pt * 65;
    float ra[NH];
#pragma unroll
    for (int k = 0; k < NH; ++k) ra[k] = myrow[k];

    const float* sw1 = (const float*)(sm + SM_B1);
    float* gout = &g_h[(size_t)n * NJ];
    const int jj0 = half * 12;
#pragma unroll 1
    for (int jj = jj0; jj < jj0 + 12; ++jj) {
        float s = 0.f;
#pragma unroll
        for (int k = 0; k < NH; ++k) s = fmaf(ra[k], sw1[k * NJ + jj], s);
        gout[jj] = fmaxf(s, 0.f);
    }
}

// ---------------------------------------------------------------------------
// Kernel 2: scrambled-weight readback + normalized transform blend
// ---------------------------------------------------------------------------
__global__ __launch_bounds__(256)
void warp_kernel(const float* __restrict__ xyz,
                 const float* __restrict__ vdir,
                 const float* __restrict__ transforms,
                 float* __restrict__ out)
{
    __shared__ float str[NJ * 16];
    const int tid = threadIdx.x;
    const int m   = blockIdx.x * 256 + tid;
    for (int i = tid; i < NJ * 16; i += 256) str[i] = transforms[i];
    __syncthreads();

    float w[NJ];
    float s = 0.f;
#pragma unroll
    for (int j = 0; j < NJ; ++j) {
        w[j] = g_h[(size_t)j * NPTS + m];
        s += w[j];
    }
    const float inv = 1.0f / (s + 1e-6f);

    const float x  = xyz[3 * m + 0], y  = xyz[3 * m + 1], z  = xyz[3 * m + 2];
    const float vx = vdir[3 * m + 0], vy = vdir[3 * m + 1], vz = vdir[3 * m + 2];
    const float x2 = x - vx, y2 = y - vy, z2 = z - vz;

    float a1x = 0.f, a1y = 0.f, a1z = 0.f;
    float a2x = 0.f, a2y = 0.f, a2z = 0.f;
#pragma unroll
    for (int j = 0; j < NJ; ++j) {
        const float wn = w[j] * inv;
        const float* T = &str[j * 16];
        a1x = fmaf(wn, fmaf(T[0], x,  fmaf(T[1], y,  fmaf(T[2],  z,  T[3]))),  a1x);
        a1y = fmaf(wn, fmaf(T[4], x,  fmaf(T[5], y,  fmaf(T[6],  z,  T[7]))),  a1y);
        a1z = fmaf(wn, fmaf(T[8], x,  fmaf(T[9], y,  fmaf(T[10], z,  T[11]))), a1z);
        a2x = fmaf(wn, fmaf(T[0], x2, fmaf(T[1], y2, fmaf(T[2],  z2, T[3]))),  a2x);
        a2y = fmaf(wn, fmaf(T[4], x2, fmaf(T[5], y2, fmaf(T[6],  z2, T[7]))),  a2y);
        a2z = fmaf(wn, fmaf(T[8], x2, fmaf(T[9], y2, fmaf(T[10], z2, T[11]))), a2z);
    }

    out[3 * m + 0] = a1x;
    out[3 * m + 1] = a1y;
    out[3 * m + 2] = a1z;
    float* o2 = out + (size_t)3 * NPTS;
    o2[3 * m + 0] = a1x - a2x;
    o2[3 * m + 1] = a1y - a2y;
    o2[3 * m + 2] = a1z - a2z;
}

// ---------------------------------------------------------------------------
// Inputs: xyz_sampled, viewdirs, transforms, ray_valid(unused), w0, w1
// ---------------------------------------------------------------------------
extern "C" void kernel_launch(void* const* d_in, const int* in_sizes, int n_in,
                              void* d_out, int out_size)
{
    const float* xyz = (const float*)d_in[0];
    const float* vd  = (const float*)d_in[1];
    const float* tr  = (const float*)d_in[2];
    const float* w0  = (const float*)d_in[4];
    const float* w1  = (const float*)d_in[5];
    float* out = (float*)d_out;

    // Unconditional every call: deterministic, not a stream op (capture-safe).
    cudaFuncSetAttribute(weights_mma, cudaFuncAttributeMaxDynamicSharedMemorySize, SM_SZ);

    prep_b<<<(NPH * KP * 72 + 255) / 256, 256>>>(w0);
    weights_mma<<<NPTS / 128, 256, SM_SZ>>>(xyz, tr, w1);
    warp_kernel<<<NPTS / 256, 256>>>(xyz, vd, tr, out);
}

// round 14
// speedup vs baseline: 1.2315x; 1.2315x over previous
#include <cuda_runtime.h>
#include <cuda_fp16.h>
#include <cstdint>
#include <math.h>

// Problem constants (R=1024, S=128, J=24, H=64, multires=6)
constexpr int NPTS = 1024 * 128;
constexpr int NJ   = 24;
constexpr int NH   = 64;
constexpr int NI   = 39;
constexpr int NPH  = 12;     // phases: 2 joints each
constexpr int KP   = 80;     // K per phase: 39 + 1 pad + 39 + 1 pad
constexpr int ASTR = 176;    // A row stride bytes (80 cols * 2B = 160, pad to 176)
constexpr int BSTR = 144;    // B row stride bytes (64 cols * 2B = 128, pad to 144)

// ---- dynamic SMEM layout (A and B both double-buffered) ----
constexpr int SM_A0  = 0;                       // 128 x 176 = 22528
constexpr int SM_A1  = 22528;                   //            45056
constexpr int SM_B0  = 45056;                   // 80 x 144 = 11520
constexpr int SM_B1  = 56576;                   //            68096
constexpr int SM_TR  = 68096;                   // 24x16 f32 = 1536
constexpr int SM_SZ  = 69632;                   // 3 CTAs/SM = 209KB
// epilogue overlays: H[128 x 65 f32] = 33280B at 0 (over A0/A1), W1 at SM_B0

// relu(h) row-major [NPTS, NJ]; warp_kernel reads the faithful view(J,-1).T
// scramble as linear index j*NPTS + m.
__device__ float g_h[(size_t)NPTS * NJ];
// fp16 B images per phase: [80 k][72 n-stride] (byte image of the smem tile)
__device__ __align__(16) unsigned short g_Bh[NPH * KP * 72];

// ---------------- helpers ----------------
__device__ __forceinline__ uint32_t smem_u32(const void* p) {
    uint32_t a;
    asm("{ .reg .u64 t; cvta.to.shared.u64 t, %1; cvt.u32.u64 %0, t; }" : "=r"(a) : "l"(p));
    return a;
}
__device__ __forceinline__ void ldsm4(uint32_t* r, uint32_t addr) {
    asm volatile("ldmatrix.sync.aligned.m8n8.x4.shared.b16 {%0,%1,%2,%3}, [%4];"
                 : "=r"(r[0]), "=r"(r[1]), "=r"(r[2]), "=r"(r[3]) : "r"(addr));
}
__device__ __forceinline__ void ldsm4t(uint32_t* r, uint32_t addr) {
    asm volatile("ldmatrix.sync.aligned.m8n8.x4.trans.shared.b16 {%0,%1,%2,%3}, [%4];"
                 : "=r"(r[0]), "=r"(r[1]), "=r"(r[2]), "=r"(r[3]) : "r"(addr));
}
__device__ __forceinline__ void mma16816h(float* d, const uint32_t* a,
                                          uint32_t b0, uint32_t b1) {
    asm volatile(
        "mma.sync.aligned.m16n8k16.row.col.f32.f16.f16.f32 "
        "{%0,%1,%2,%3}, {%4,%5,%6,%7}, {%8,%9}, {%0,%1,%2,%3};"
        : "+f"(d[0]), "+f"(d[1]), "+f"(d[2]), "+f"(d[3])
        : "r"(a[0]), "r"(a[1]), "r"(a[2]), "r"(a[3]), "r"(b0), "r"(b1));
}
// pack two f32 -> f16x2 (a in low half)
__device__ __forceinline__ uint32_t packh2(float a, float b) {
    uint32_t r;
    asm("cvt.rn.f16x2.f32 %0, %1, %2;" : "=r"(r) : "f"(b), "f"(a));
    return r;
}

// ---------------------------------------------------------------------------
// Prep: per-phase B tiles: k rows 0..38 = joint 2p, 39 zero, 40..78 = joint
// 2p+1, 79 zero.  B[k][n] = fp16(w0[(j*39+k)*64 + n]); pad cols zeroed.
// ---------------------------------------------------------------------------
__global__ void prep_b(const float* __restrict__ w0) {
    int idx = blockIdx.x * 256 + threadIdx.x;
    if (idx >= NPH * KP * 72) return;
    int p = idx / (KP * 72), rem = idx % (KP * 72);
    int kk = rem / 72, n = rem % 72;
    float v = 0.f;
    if (n < NH) {
        if (kk < NI)                  v = w0[((2 * p)     * NI + kk)        * NH + n];
        else if (kk >= 40 && kk < 79) v = w0[((2 * p + 1) * NI + (kk - 40)) * NH + n];
    }
    g_Bh[p * (KP * 72) + kk * 72 + n] = __half_as_ushort(__float2half_rn(v));
}

// ---------------------------------------------------------------------------
// Kernel 1: 128-pt tile, 256 threads (8 warps), 3 CTAs/SM.
// A and B double-buffered => ONE __syncthreads per phase:
//   per warp: [stage B(p) | features -> A(p)] ; sync ; gemm(p)
// Feature work: thread (pt, half) computes joint 2p+half of point pt.
// GEMM: single-pass fp16 D = Ah*Bh. Warp w: rows (w&3)*32, cols (w>>2)*32.
// ---------------------------------------------------------------------------
__global__ __launch_bounds__(256, 3)
void weights_mma(const float* __restrict__ xyz,
                 const float* __restrict__ transforms,
                 const float* __restrict__ w1)
{
    extern __shared__ __align__(16) char sm[];
    const uint32_t sb = smem_u32(sm);
    const int tid = threadIdx.x, lane = tid & 31, w = tid >> 5;
    const int pt = tid & 127, half = tid >> 7;
    const int wr = w & 3, wc = w >> 2;
    const int n = blockIdx.x * 128 + pt;
    const int oct = lane >> 3, oi = lane & 7;

    for (int i = tid; i < NJ * 16; i += 256)
        ((float*)(sm + SM_TR))[i] = transforms[i];
    __syncthreads();

    const float x = xyz[3 * n + 0];
    const float y = xyz[3 * n + 1];
    const float z = xyz[3 * n + 2];

    float acc[2][4][4];
#pragma unroll
    for (int a = 0; a < 2; ++a)
#pragma unroll
        for (int b = 0; b < 4; ++b)
#pragma unroll
            for (int c = 0; c < 4; ++c) acc[a][b][c] = 0.f;

    for (int p = 0; p < NPH; ++p) {
        const int bB = (p & 1) ? SM_B1 : SM_B0;
        const int bA = (p & 1) ? SM_A1 : SM_A0;

        // stage this phase's B tile: 80 rows x 144B = 720 uint4 (FULL tile)
        // (writes go to the buffer gemm(p-1) is NOT reading)
        {
            const uint4* shp = (const uint4*)(g_Bh + p * (KP * 72));
            uint4* dh = (uint4*)(sm + bB);
            for (int i = tid; i < 720; i += 256) dh[i] = shp[i];
        }

        // features for joint (2p + half), packed to fp16 pairs on the fly
        uint32_t fp[20];
        {
            const int j = 2 * p + half;
            const float* T = (const float*)(sm + SM_TR) + j * 16;
            float lx = fmaf(T[0], x, fmaf(T[1], y, fmaf(T[2],  z, T[3])));
            float ly = fmaf(T[4], x, fmaf(T[5], y, fmaf(T[6],  z, T[7])));
            float lz = fmaf(T[8], x, fmaf(T[9], y, fmaf(T[10], z, T[11])));
            const float INV = 2.0f / 3.0f;
            lx = (lx + 1.5f) * INV - 1.0f;
            ly = (ly + 1.5f) * INV - 1.0f;
            lz = (lz + 1.5f) * INV - 1.0f;
            fp[0] = packh2(lx, ly);
            float carry = lz;                       // index 2, awaits sx0
            float sx, cx, sy, cy, sz, cz;
            __sincosf(lx, &sx, &cx);
            __sincosf(ly, &sy, &cy);
            __sincosf(lz, &sz, &cz);
#pragma unroll
            for (int ff = 0; ff < 6; ++ff) {
                fp[1 + 3 * ff] = packh2(carry, sx);
                fp[2 + 3 * ff] = packh2(sy, sz);
                fp[3 + 3 * ff] = packh2(cx, cy);
                carry = cz;
                if (ff < 5) {
                    // sin(2a) = 2 s c ; cos(2a) = 1 - 2 s^2
                    float nsx = 2.f * sx * cx, ncx = fmaf(-2.f * sx, sx, 1.f);
                    float nsy = 2.f * sy * cy, ncy = fmaf(-2.f * sy, sy, 1.f);
                    float nsz = 2.f * sz * cz, ncz = fmaf(-2.f * sz, sz, 1.f);
                    sx = nsx; cx = ncx; sy = nsy; cy = ncy; sz = nsz; cz = ncz;
                }
            }
            fp[19] = packh2(carry, 0.f);            // cz5 + pad column
        }

        // store this thread's fp16 A half-row (5 x 16B) into buffer p&1
#pragma unroll
        for (int c = 0; c < 5; ++c) {
            uint4 H = make_uint4(fp[4 * c + 0], fp[4 * c + 1],
                                 fp[4 * c + 2], fp[4 * c + 3]);
            *(uint4*)(sm + bA + pt * ASTR + half * 80 + c * 16) = H;
        }
        __syncthreads();   // A(p) + B(p) staged by all; gemm(p-1) fully done

        // ldmatrix + mma: warp computes rows [wr*32,+32) x cols [wc*32,+32)
#pragma unroll
        for (int ks = 0; ks < 5; ++ks) {
            uint32_t ah[2][4];
#pragma unroll
            for (int mt = 0; mt < 2; ++mt) {
                uint32_t ra = (uint32_t)((wr * 32 + mt * 16 + (oct & 1) * 8 + oi) * ASTR
                                         + ks * 32 + (oct >> 1) * 16);
                ldsm4(ah[mt], sb + bA + ra);
            }
#pragma unroll
            for (int np = 0; np < 2; ++np) {
                uint32_t rb = (uint32_t)((ks * 16 + (oct & 1) * 8 + oi) * BSTR
                                         + wc * 64 + np * 32 + (oct >> 1) * 16);
                uint32_t bh[4];
                ldsm4t(bh, sb + bB + rb);
#pragma unroll
                for (int mt = 0; mt < 2; ++mt) {
                    mma16816h(acc[mt][2 * np + 0], ah[mt], bh[0], bh[1]);
                    mma16816h(acc[mt][2 * np + 1], ah[mt], bh[2], bh[3]);
                }
            }
        }
    }
    __syncthreads();   // all warps done with A/B regions

    // Epilogue: relu(acc) -> H smem [128 x 64], stride 65 f32 (overlays A0/A1)
    float* hs = (float*)(sm + 0);
#pragma unroll
    for (int mt = 0; mt < 2; ++mt) {
        const int rr = wr * 32 + mt * 16 + (lane >> 2);
#pragma unroll
        for (int nt = 0; nt < 4; ++nt) {
            const int cc = wc * 32 + nt * 8 + (lane & 3) * 2;
            hs[rr * 65 + cc]           = fmaxf(acc[mt][nt][0], 0.f);
            hs[rr * 65 + cc + 1]       = fmaxf(acc[mt][nt][1], 0.f);
            hs[(rr + 8) * 65 + cc]     = fmaxf(acc[mt][nt][2], 0.f);
            hs[(rr + 8) * 65 + cc + 1] = fmaxf(acc[mt][nt][3], 0.f);
        }
    }
    for (int i = tid; i < (NH * NJ) / 4; i += 256)
        ((float4*)(sm + SM_B0))[i] = ((const float4*)w1)[i];
    __syncthreads();

    // Layer 2 + relu: thread (pt, half) does row pt, jj in [half*12, half*12+12)
    const float* myrow = hs + pt * 65;
    float ra[NH];
#pragma unroll
    for (int k = 0; k < NH; ++k) ra[k] = myrow[k];

    const float* sw1 = (const float*)(sm + SM_B0);
    float* gout = &g_h[(size_t)n * NJ];
    const int jj0 = half * 12;
#pragma unroll 1
    for (int jj = jj0; jj < jj0 + 12; ++jj) {
        float s = 0.f;
#pragma unroll
        for (int k = 0; k < NH; ++k) s = fmaf(ra[k], sw1[k * NJ + jj], s);
        gout[jj] = fmaxf(s, 0.f);
    }
}

// ---------------------------------------------------------------------------
// Kernel 2: scrambled-weight readback + normalized transform blend
// ---------------------------------------------------------------------------
__global__ __launch_bounds__(256)
void warp_kernel(const float* __restrict__ xyz,
                 const float* __restrict__ vdir,
                 const float* __restrict__ transforms,
                 float* __restrict__ out)
{
    __shared__ float str[NJ * 16];
    const int tid = threadIdx.x;
    const int m   = blockIdx.x * 256 + tid;
    for (int i = tid; i < NJ * 16; i += 256) str[i] = transforms[i];
    __syncthreads();

    float w[NJ];
    float s = 0.f;
#pragma unroll
    for (int j = 0; j < NJ; ++j) {
        w[j] = g_h[(size_t)j * NPTS + m];
        s += w[j];
    }
    const float inv = 1.0f / (s + 1e-6f);

    const float x  = xyz[3 * m + 0], y  = xyz[3 * m + 1], z  = xyz[3 * m + 2];
    const float vx = vdir[3 * m + 0], vy = vdir[3 * m + 1], vz = vdir[3 * m + 2];
    const float x2 = x - vx, y2 = y - vy, z2 = z - vz;

    float a1x = 0.f, a1y = 0.f, a1z = 0.f;
    float a2x = 0.f, a2y = 0.f, a2z = 0.f;
#pragma unroll
    for (int j = 0; j < NJ; ++j) {
        const float wn = w[j] * inv;
        const float* T = &str[j * 16];
        a1x = fmaf(wn, fmaf(T[0], x,  fmaf(T[1], y,  fmaf(T[2],  z,  T[3]))),  a1x);
        a1y = fmaf(wn, fmaf(T[4], x,  fmaf(T[5], y,  fmaf(T[6],  z,  T[7]))),  a1y);
        a1z = fmaf(wn, fmaf(T[8], x,  fmaf(T[9], y,  fmaf(T[10], z,  T[11]))), a1z);
        a2x = fmaf(wn, fmaf(T[0], x2, fmaf(T[1], y2, fmaf(T[2],  z2, T[3]))),  a2x);
        a2y = fmaf(wn, fmaf(T[4], x2, fmaf(T[5], y2, fmaf(T[6],  z2, T[7]))),  a2y);
        a2z = fmaf(wn, fmaf(T[8], x2, fmaf(T[9], y2, fmaf(T[10], z2, T[11]))), a2z);
    }

    out[3 * m + 0] = a1x;
    out[3 * m + 1] = a1y;
    out[3 * m + 2] = a1z;
    float* o2 = out + (size_t)3 * NPTS;
    o2[3 * m + 0] = a1x - a2x;
    o2[3 * m + 1] = a1y - a2y;
    o2[3 * m + 2] = a1z - a2z;
}

// ---------------------------------------------------------------------------
// Inputs: xyz_sampled, viewdirs, transforms, ray_valid(unused), w0, w1
// ---------------------------------------------------------------------------
extern "C" void kernel_launch(void* const* d_in, const int* in_sizes, int n_in,
                              void* d_out, int out_size)
{
    const float* xyz = (const float*)d_in[0];
    const float* vd  = (const float*)d_in[1];
    const float* tr  = (const float*)d_in[2];
    const float* w0  = (const float*)d_in[4];
    const float* w1  = (const float*)d_in[5];
    float* out = (float*)d_out;

    // Unconditional every call: deterministic, not a stream op (capture-safe).
    cudaFuncSetAttribute(weights_mma, cudaFuncAttributeMaxDynamicSharedMemorySize, SM_SZ);

    prep_b<<<(NPH * KP * 72 + 255) / 256, 256>>>(w0);
    weights_mma<<<NPTS / 128, 256, SM_SZ>>>(xyz, tr, w1);
    warp_kernel<<<NPTS / 256, 256>>>(xyz, vd, tr, out);
}

// round 15
// speedup vs baseline: 1.3566x; 1.1016x over previous
#include <cuda_runtime.h>
#include <cuda_fp16.h>
#include <cstdint>
#include <math.h>

// Problem constants (R=1024, S=128, J=24, H=64, multires=6)
constexpr int NPTS = 1024 * 128;
constexpr int NJ   = 24;
constexpr int NH   = 64;
constexpr int NI   = 39;
constexpr int NPH  = 12;     // phases: 2 joints each
constexpr int KP   = 80;     // K per phase: 39 + 1 pad + 39 + 1 pad
constexpr int ASTR = 176;    // A row stride bytes (80 cols * 2B = 160, pad to 176)
constexpr int BSTR = 144;    // B row stride bytes (64 cols * 2B = 128, pad to 144)

// ---- dynamic SMEM layout (A and B both double-buffered) ----
constexpr int SM_A0  = 0;                       // 128 x 176 = 22528
constexpr int SM_A1  = 22528;                   //            45056
constexpr int SM_B0  = 45056;                   // 80 x 144 = 11520
constexpr int SM_B1  = 56576;                   //            68096
constexpr int SM_TR  = 68096;                   // 24x16 f32 = 1536
constexpr int SM_SZ  = 69632;                   // 3 CTAs/SM = 209KB
// epilogue overlays: H[128 x 65 f32] = 33280B at 0 (over A0/A1), W1 at SM_B0

// relu(h) row-major [NPTS, NJ]; warp_kernel reads the faithful view(J,-1).T
// scramble as linear index j*NPTS + m.
__device__ float g_h[(size_t)NPTS * NJ];
// fp16 B images per phase: [80 k][72 n-stride] (byte image of the smem tile)
__device__ __align__(16) unsigned short g_Bh[NPH * KP * 72];

// ---------------- helpers ----------------
__device__ __forceinline__ uint32_t smem_u32(const void* p) {
    uint32_t a;
    asm("{ .reg .u64 t; cvta.to.shared.u64 t, %1; cvt.u32.u64 %0, t; }" : "=r"(a) : "l"(p));
    return a;
}
__device__ __forceinline__ void ldsm4(uint32_t* r, uint32_t addr) {
    asm volatile("ldmatrix.sync.aligned.m8n8.x4.shared.b16 {%0,%1,%2,%3}, [%4];"
                 : "=r"(r[0]), "=r"(r[1]), "=r"(r[2]), "=r"(r[3]) : "r"(addr));
}
__device__ __forceinline__ void ldsm4t(uint32_t* r, uint32_t addr) {
    asm volatile("ldmatrix.sync.aligned.m8n8.x4.trans.shared.b16 {%0,%1,%2,%3}, [%4];"
                 : "=r"(r[0]), "=r"(r[1]), "=r"(r[2]), "=r"(r[3]) : "r"(addr));
}
__device__ __forceinline__ void mma16816h(float* d, const uint32_t* a,
                                          uint32_t b0, uint32_t b1) {
    asm volatile(
        "mma.sync.aligned.m16n8k16.row.col.f32.f16.f16.f32 "
        "{%0,%1,%2,%3}, {%4,%5,%6,%7}, {%8,%9}, {%0,%1,%2,%3};"
        : "+f"(d[0]), "+f"(d[1]), "+f"(d[2]), "+f"(d[3])
        : "r"(a[0]), "r"(a[1]), "r"(a[2]), "r"(a[3]), "r"(b0), "r"(b1));
}
// pack two f32 -> f16x2 (a in low half)
__device__ __forceinline__ uint32_t packh2(float a, float b) {
    uint32_t r;
    asm("cvt.rn.f16x2.f32 %0, %1, %2;" : "=r"(r) : "f"(b), "f"(a));
    return r;
}
__device__ __forceinline__ void cpasync16(uint32_t dst, const void* src) {
    asm volatile("cp.async.cg.shared.global [%0], [%1], 16;"
                 :: "r"(dst), "l"(src) : "memory");
}
#define CP_COMMIT() asm volatile("cp.async.commit_group;" ::: "memory")
#define CP_WAIT0()  asm volatile("cp.async.wait_group 0;" ::: "memory")

// ---------------------------------------------------------------------------
// Prep: per-phase B tiles: k rows 0..38 = joint 2p, 39 zero, 40..78 = joint
// 2p+1, 79 zero.  B[k][n] = fp16(w0[(j*39+k)*64 + n]); pad cols zeroed.
// ---------------------------------------------------------------------------
__global__ void prep_b(const float* __restrict__ w0) {
    int idx = blockIdx.x * 256 + threadIdx.x;
    if (idx >= NPH * KP * 72) return;
    int p = idx / (KP * 72), rem = idx % (KP * 72);
    int kk = rem / 72, n = rem % 72;
    float v = 0.f;
    if (n < NH) {
        if (kk < NI)                  v = w0[((2 * p)     * NI + kk)        * NH + n];
        else if (kk >= 40 && kk < 79) v = w0[((2 * p + 1) * NI + (kk - 40)) * NH + n];
    }
    g_Bh[p * (KP * 72) + kk * 72 + n] = __half_as_ushort(__float2half_rn(v));
}

// ---------------------------------------------------------------------------
// Kernel 1: 128-pt tile, 256 threads (8 warps), 3 CTAs/SM.
// A/B double-buffered, B staged via cp.async one phase ahead:
//   phase p: [cp.async B(p+1) | gemm(p) | features(p+1)->A(p+1) | wait+sync]
// Feature work: thread (pt, half) computes joint 2p+half of point pt.
// GEMM: single-pass fp16 D = Ah*Bh. Warp w: rows (w&3)*32, cols (w>>2)*32.
// ---------------------------------------------------------------------------
__global__ __launch_bounds__(256, 3)
void weights_mma(const float* __restrict__ xyz,
                 const float* __restrict__ transforms,
                 const float* __restrict__ w1)
{
    extern __shared__ __align__(16) char sm[];
    const uint32_t sb = smem_u32(sm);
    const int tid = threadIdx.x, lane = tid & 31, w = tid >> 5;
    const int pt = tid & 127, half = tid >> 7;
    const int wr = w & 3, wc = w >> 2;
    const int n = blockIdx.x * 128 + pt;
    const int oct = lane >> 3, oi = lane & 7;

    for (int i = tid; i < NJ * 16; i += 256)
        ((float*)(sm + SM_TR))[i] = transforms[i];
    __syncthreads();

    const float x = xyz[3 * n + 0];
    const float y = xyz[3 * n + 1];
    const float z = xyz[3 * n + 2];

    // features for joint j of this thread's point -> A row (buffer bA)
    auto do_features = [&](int p) {
        const int j = 2 * p + half;
        const int bA = (p & 1) ? SM_A1 : SM_A0;
        const float* T = (const float*)(sm + SM_TR) + j * 16;
        float lx = fmaf(T[0], x, fmaf(T[1], y, fmaf(T[2],  z, T[3])));
        float ly = fmaf(T[4], x, fmaf(T[5], y, fmaf(T[6],  z, T[7])));
        float lz = fmaf(T[8], x, fmaf(T[9], y, fmaf(T[10], z, T[11])));
        const float INV = 2.0f / 3.0f;
        lx = (lx + 1.5f) * INV - 1.0f;
        ly = (ly + 1.5f) * INV - 1.0f;
        lz = (lz + 1.5f) * INV - 1.0f;
        uint32_t fp[20];
        fp[0] = packh2(lx, ly);
        float carry = lz;                       // index 2, awaits sx0
        float sx, cx, sy, cy, sz, cz;
        __sincosf(lx, &sx, &cx);
        __sincosf(ly, &sy, &cy);
        __sincosf(lz, &sz, &cz);
#pragma unroll
        for (int ff = 0; ff < 6; ++ff) {
            fp[1 + 3 * ff] = packh2(carry, sx);
            fp[2 + 3 * ff] = packh2(sy, sz);
            fp[3 + 3 * ff] = packh2(cx, cy);
            carry = cz;
            if (ff < 5) {
                // sin(2a) = 2 s c ; cos(2a) = 1 - 2 s^2
                float nsx = 2.f * sx * cx, ncx = fmaf(-2.f * sx, sx, 1.f);
                float nsy = 2.f * sy * cy, ncy = fmaf(-2.f * sy, sy, 1.f);
                float nsz = 2.f * sz * cz, ncz = fmaf(-2.f * sz, sz, 1.f);
                sx = nsx; cx = ncx; sy = nsy; cy = ncy; sz = nsz; cz = ncz;
            }
        }
        fp[19] = packh2(carry, 0.f);            // cz5 + pad column
#pragma unroll
        for (int c = 0; c < 5; ++c) {
            uint4 H = make_uint4(fp[4 * c + 0], fp[4 * c + 1],
                                 fp[4 * c + 2], fp[4 * c + 3]);
            *(uint4*)(sm + bA + pt * ASTR + half * 80 + c * 16) = H;
        }
    };
    // stage B(p) into its buffer via cp.async (fire-and-forget)
    auto stage_b = [&](int p) {
        const int bB = (p & 1) ? SM_B1 : SM_B0;
        const char* src = (const char*)(g_Bh + p * (KP * 72));
        for (int i = tid * 16; i < 11520; i += 256 * 16)
            cpasync16(sb + bB + i, src + i);
        CP_COMMIT();
    };

    float acc[2][4][4];
#pragma unroll
    for (int a = 0; a < 2; ++a)
#pragma unroll
        for (int b = 0; b < 4; ++b)
#pragma unroll
            for (int c = 0; c < 4; ++c) acc[a][b][c] = 0.f;

    // prologue: B(0) + A(0)
    stage_b(0);
    do_features(0);
    CP_WAIT0();
    __syncthreads();

    for (int p = 0; p < NPH; ++p) {
        const int bB = (p & 1) ? SM_B1 : SM_B0;
        const int bA = (p & 1) ? SM_A1 : SM_A0;

        // prefetch next phase's B early: overlaps gemm(p) + features(p+1).
        // Target buffer was last read by gemm(p-1); the sync above proved done.
        if (p + 1 < NPH) stage_b(p + 1);

        // gemm(p): warp computes rows [wr*32,+32) x cols [wc*32,+32)
#pragma unroll
        for (int ks = 0; ks < 5; ++ks) {
            uint32_t ah[2][4];
#pragma unroll
            for (int mt = 0; mt < 2; ++mt) {
                uint32_t ra = (uint32_t)((wr * 32 + mt * 16 + (oct & 1) * 8 + oi) * ASTR
                                         + ks * 32 + (oct >> 1) * 16);
                ldsm4(ah[mt], sb + bA + ra);
            }
#pragma unroll
            for (int np = 0; np < 2; ++np) {
                uint32_t rb = (uint32_t)((ks * 16 + (oct & 1) * 8 + oi) * BSTR
                                         + wc * 64 + np * 32 + (oct >> 1) * 16);
                uint32_t bh[4];
                ldsm4t(bh, sb + bB + rb);
#pragma unroll
                for (int mt = 0; mt < 2; ++mt) {
                    mma16816h(acc[mt][2 * np + 0], ah[mt], bh[0], bh[1]);
                    mma16816h(acc[mt][2 * np + 1], ah[mt], bh[2], bh[3]);
                }
            }
        }

        if (p + 1 < NPH) {
            do_features(p + 1);   // writes A buffer (p+1)&1 — gemm(p-1)'s, done
            CP_WAIT0();           // B(p+1) landed
            __syncthreads();      // publish A(p+1)+B(p+1); all gemm(p) done
        }
    }
    __syncthreads();   // all warps done with A/B regions

    // Epilogue: relu(acc) -> H smem [128 x 64], stride 65 f32 (overlays A0/A1)
    float* hs = (float*)(sm + 0);
#pragma unroll
    for (int mt = 0; mt < 2; ++mt) {
        const int rr = wr * 32 + mt * 16 + (lane >> 2);
#pragma unroll
        for (int nt = 0; nt < 4; ++nt) {
            const int cc = wc * 32 + nt * 8 + (lane & 3) * 2;
            hs[rr * 65 + cc]           = fmaxf(acc[mt][nt][0], 0.f);
            hs[rr * 65 + cc + 1]       = fmaxf(acc[mt][nt][1], 0.f);
            hs[(rr + 8) * 65 + cc]     = fmaxf(acc[mt][nt][2], 0.f);
            hs[(rr + 8) * 65 + cc + 1] = fmaxf(acc[mt][nt][3], 0.f);
        }
    }
    for (int i = tid; i < (NH * NJ) / 4; i += 256)
        ((float4*)(sm + SM_B0))[i] = ((const float4*)w1)[i];
    __syncthreads();

    // Layer 2 + relu: thread (pt, half) does row pt, jj in [half*12, half*12+12)
    const float* myrow = hs + pt * 65;
    float ra[NH];
#pragma unroll
    for (int k = 0; k < NH; ++k) ra[k] = myrow[k];

    const float* sw1 = (const float*)(sm + SM_B0);
    float* gout = &g_h[(size_t)n * NJ];
    const int jj0 = half * 12;
#pragma unroll 1
    for (int jj = jj0; jj < jj0 + 12; ++jj) {
        float s = 0.f;
#pragma unroll
        for (int k = 0; k < NH; ++k) s = fmaf(ra[k], sw1[k * NJ + jj], s);
        gout[jj] = fmaxf(s, 0.f);
    }
}

// ---------------------------------------------------------------------------
// Kernel 2: scrambled-weight readback + normalized transform blend
// ---------------------------------------------------------------------------
__global__ __launch_bounds__(256)
void warp_kernel(const float* __restrict__ xyz,
                 const float* __restrict__ vdir,
                 const float* __restrict__ transforms,
                 float* __restrict__ out)
{
    __shared__ float str[NJ * 16];
    const int tid = threadIdx.x;
    const int m   = blockIdx.x * 256 + tid;
    for (int i = tid; i < NJ * 16; i += 256) str[i] = transforms[i];
    __syncthreads();

    float w[NJ];
    float s = 0.f;
#pragma unroll
    for (int j = 0; j < NJ; ++j) {
        w[j] = g_h[(size_t)j * NPTS + m];
        s += w[j];
    }
    const float inv = 1.0f / (s + 1e-6f);

    const float x  = xyz[3 * m + 0], y  = xyz[3 * m + 1], z  = xyz[3 * m + 2];
    const float vx = vdir[3 * m + 0], vy = vdir[3 * m + 1], vz = vdir[3 * m + 2];
    const float x2 = x - vx, y2 = y - vy, z2 = z - vz;

    float a1x = 0.f, a1y = 0.f, a1z = 0.f;
    float a2x = 0.f, a2y = 0.f, a2z = 0.f;
#pragma unroll
    for (int j = 0; j < NJ; ++j) {
        const float wn = w[j] * inv;
        const float* T = &str[j * 16];
        a1x = fmaf(wn, fmaf(T[0], x,  fmaf(T[1], y,  fmaf(T[2],  z,  T[3]))),  a1x);
        a1y = fmaf(wn, fmaf(T[4], x,  fmaf(T[5], y,  fmaf(T[6],  z,  T[7]))),  a1y);
        a1z = fmaf(wn, fmaf(T[8], x,  fmaf(T[9], y,  fmaf(T[10], z,  T[11]))), a1z);
        a2x = fmaf(wn, fmaf(T[0], x2, fmaf(T[1], y2, fmaf(T[2],  z2, T[3]))),  a2x);
        a2y = fmaf(wn, fmaf(T[4], x2, fmaf(T[5], y2, fmaf(T[6],  z2, T[7]))),  a2y);
        a2z = fmaf(wn, fmaf(T[8], x2, fmaf(T[9], y2, fmaf(T[10], z2, T[11]))), a2z);
    }

    out[3 * m + 0] = a1x;
    out[3 * m + 1] = a1y;
    out[3 * m + 2] = a1z;
    float* o2 = out + (size_t)3 * NPTS;
    o2[3 * m + 0] = a1x - a2x;
    o2[3 * m + 1] = a1y - a2y;
    o2[3 * m + 2] = a1z - a2z;
}

// ---------------------------------------------------------------------------
// Inputs: xyz_sampled, viewdirs, transforms, ray_valid(unused), w0, w1
// ---------------------------------------------------------------------------
extern "C" void kernel_launch(void* const* d_in, const int* in_sizes, int n_in,
                              void* d_out, int out_size)
{
    const float* xyz = (const float*)d_in[0];
    const float* vd  = (const float*)d_in[1];
    const float* tr  = (const float*)d_in[2];
    const float* w0  = (const float*)d_in[4];
    const float* w1  = (const float*)d_in[5];
    float* out = (float*)d_out;

    // Unconditional every call: deterministic, not a stream op (capture-safe).
    cudaFuncSetAttribute(weights_mma, cudaFuncAttributeMaxDynamicSharedMemorySize, SM_SZ);

    prep_b<<<(NPH * KP * 72 + 255) / 256, 256>>>(w0);
    weights_mma<<<NPTS / 128, 256, SM_SZ>>>(xyz, tr, w1);
    warp_kernel<<<NPTS / 256, 256>>>(xyz, vd, tr, out);
}

// round 17
// speedup vs baseline: 1.8276x; 1.3471x over previous
#include <cuda_runtime.h>
#include <cuda_fp16.h>
#include <cstdint>
#include <math.h>

// Problem constants (R=1024, S=128, J=24, H=64, multires=6)
constexpr int NPTS = 1024 * 128;
constexpr int NJ   = 24;
constexpr int NH   = 64;
constexpr int NI   = 39;
constexpr int NPH  = 12;     // phases: 2 joints each
constexpr int KP   = 80;     // K per phase: 39 + 1 pad + 39 + 1 pad
constexpr int ASTR = 176;    // A row stride bytes
constexpr int BSTR = 144;    // B row stride bytes
constexpr int HSTR = 144;    // H row stride bytes (epilogue A operand)
constexpr int B2STR = 80;    // w1 tile row stride bytes (32 n cols padded to 40)

// ---- dynamic SMEM layout (A and B double-buffered) ----
constexpr int SM_A0  = 0;                       // 128 x 176 = 22528
constexpr int SM_A1  = 22528;                   //            45056
constexpr int SM_B0  = 45056;                   // 80 x 144 = 11520
constexpr int SM_B1  = 56576;                   //            68096
constexpr int SM_TR  = 68096;                   // 24x16 f32 = 1536
constexpr int SM_SZ  = 69632;                   // 3 CTAs/SM
// epilogue overlays: Hh[128x144B]=18432 at 0, Hl at 18432 (ends 36864 < 45056)
//                    B2h at 45056 (64x80=5120), B2l at 50176 (ends 55296)
constexpr int SM_HH  = 0;
constexpr int SM_HL  = 18432;
constexpr int SM_B2H = 45056;
constexpr int SM_B2L = 50176;

// relu(h) row-major [NPTS, NJ]; warp_kernel reads the faithful view(J,-1).T
// scramble as linear index j*NPTS + m.
__device__ float g_h[(size_t)NPTS * NJ];
// fp16 B images per phase: [80 k][72 n-stride] (byte image of the smem tile)
__device__ __align__(16) unsigned short g_Bh[NPH * KP * 72];
// fp16 hi/lo w1 tiles: [64 k][40 n-stride]
__device__ __align__(16) unsigned short g_B2h[64 * 40];
__device__ __align__(16) unsigned short g_B2l[64 * 40];

// ---------------- helpers ----------------
__device__ __forceinline__ uint32_t smem_u32(const void* p) {
    uint32_t a;
    asm("{ .reg .u64 t; cvta.to.shared.u64 t, %1; cvt.u32.u64 %0, t; }" : "=r"(a) : "l"(p));
    return a;
}
__device__ __forceinline__ void ldsm4(uint32_t* r, uint32_t addr) {
    asm volatile("ldmatrix.sync.aligned.m8n8.x4.shared.b16 {%0,%1,%2,%3}, [%4];"
                 : "=r"(r[0]), "=r"(r[1]), "=r"(r[2]), "=r"(r[3]) : "r"(addr));
}
__device__ __forceinline__ void ldsm4t(uint32_t* r, uint32_t addr) {
    asm volatile("ldmatrix.sync.aligned.m8n8.x4.trans.shared.b16 {%0,%1,%2,%3}, [%4];"
                 : "=r"(r[0]), "=r"(r[1]), "=r"(r[2]), "=r"(r[3]) : "r"(addr));
}
__device__ __forceinline__ void mma16816h(float* d, const uint32_t* a,
                                          uint32_t b0, uint32_t b1) {
    asm volatile(
        "mma.sync.aligned.m16n8k16.row.col.f32.f16.f16.f32 "
        "{%0,%1,%2,%3}, {%4,%5,%6,%7}, {%8,%9}, {%0,%1,%2,%3};"
        : "+f"(d[0]), "+f"(d[1]), "+f"(d[2]), "+f"(d[3])
        : "r"(a[0]), "r"(a[1]), "r"(a[2]), "r"(a[3]), "r"(b0), "r"(b1));
}
// pack two f32 -> f16x2 (a in low half)
__device__ __forceinline__ uint32_t packh2(float a, float b) {
    uint32_t r;
    asm("cvt.rn.f16x2.f32 %0, %1, %2;" : "=r"(r) : "f"(b), "f"(a));
    return r;
}
__device__ __forceinline__ void cpasync16(uint32_t dst, const void* src) {
    asm volatile("cp.async.cg.shared.global [%0], [%1], 16;"
                 :: "r"(dst), "l"(src) : "memory");
}
#define CP_COMMIT() asm volatile("cp.async.commit_group;" ::: "memory")
#define CP_WAIT0()  asm volatile("cp.async.wait_group 0;" ::: "memory")

// ---------------------------------------------------------------------------
// Prep: per-phase B tiles (fp16 image of w0 slices) + w1 hi/lo tiles.
// ---------------------------------------------------------------------------
__global__ void prep_b(const float* __restrict__ w0, const float* __restrict__ w1) {
    int idx = blockIdx.x * 256 + threadIdx.x;
    if (idx < NPH * KP * 72) {
        int p = idx / (KP * 72), rem = idx % (KP * 72);
        int kk = rem / 72, n = rem % 72;
        float v = 0.f;
        if (n < NH) {
            if (kk < NI)                  v = w0[((2 * p)     * NI + kk)        * NH + n];
            else if (kk >= 40 && kk < 79) v = w0[((2 * p + 1) * NI + (kk - 40)) * NH + n];
        }
        g_Bh[p * (KP * 72) + kk * 72 + n] = __half_as_ushort(__float2half_rn(v));
    } else {
        int i2 = idx - NPH * KP * 72;
        if (i2 < 64 * 40) {
            int kk = i2 / 40, n = i2 % 40;
            float v = (n < NJ) ? w1[kk * NJ + n] : 0.f;
            __half h = __float2half_rn(v);
            float r = v - __half2float(h);
            g_B2h[i2] = __half_as_ushort(h);
            g_B2l[i2] = __half_as_ushort(__float2half_rn(r));
        }
    }
}

// ---------------------------------------------------------------------------
// Kernel 1: 128-pt tile, 256 threads (8 warps), 3 CTAs/SM.
// Mainloop as R15 (cp.async B one phase ahead, A/B double-buffered, 1 sync).
// Epilogue: layer-2 on tensor cores via fp16 hi/lo 3-pass split.
// ---------------------------------------------------------------------------
__global__ __launch_bounds__(256, 3)
void weights_mma(const float* __restrict__ xyz,
                 const float* __restrict__ transforms)
{
    extern __shared__ __align__(16) char sm[];
    const uint32_t sb = smem_u32(sm);
    const int tid = threadIdx.x, lane = tid & 31, w = tid >> 5;
    const int pt = tid & 127, half = tid >> 7;
    const int wr = w & 3, wc = w >> 2;
    const int n = blockIdx.x * 128 + pt;
    const int oct = lane >> 3, oi = lane & 7;

    for (int i = tid; i < NJ * 16; i += 256)
        ((float*)(sm + SM_TR))[i] = transforms[i];
    __syncthreads();

    const float x = xyz[3 * n + 0];
    const float y = xyz[3 * n + 1];
    const float z = xyz[3 * n + 2];

    // features for joint j of this thread's point -> A row (buffer bA)
    auto do_features = [&](int p) {
        const int j = 2 * p + half;
        const int bA = (p & 1) ? SM_A1 : SM_A0;
        const float* T = (const float*)(sm + SM_TR) + j * 16;
        float lx = fmaf(T[0], x, fmaf(T[1], y, fmaf(T[2],  z, T[3])));
        float ly = fmaf(T[4], x, fmaf(T[5], y, fmaf(T[6],  z, T[7])));
        float lz = fmaf(T[8], x, fmaf(T[9], y, fmaf(T[10], z, T[11])));
        const float INV = 2.0f / 3.0f;
        lx = (lx + 1.5f) * INV - 1.0f;
        ly = (ly + 1.5f) * INV - 1.0f;
        lz = (lz + 1.5f) * INV - 1.0f;
        uint32_t fp[20];
        fp[0] = packh2(lx, ly);
        float carry = lz;
        float sx, cx, sy, cy, sz, cz;
        __sincosf(lx, &sx, &cx);
        __sincosf(ly, &sy, &cy);
        __sincosf(lz, &sz, &cz);
#pragma unroll
        for (int ff = 0; ff < 6; ++ff) {
            fp[1 + 3 * ff] = packh2(carry, sx);
            fp[2 + 3 * ff] = packh2(sy, sz);
            fp[3 + 3 * ff] = packh2(cx, cy);
            carry = cz;
            if (ff < 5) {
                // sin(2a) = 2 s c ; cos(2a) = 1 - 2 s^2
                float nsx = 2.f * sx * cx, ncx = fmaf(-2.f * sx, sx, 1.f);
                float nsy = 2.f * sy * cy, ncy = fmaf(-2.f * sy, sy, 1.f);
                float nsz = 2.f * sz * cz, ncz = fmaf(-2.f * sz, sz, 1.f);
                sx = nsx; cx = ncx; sy = nsy; cy = ncy; sz = nsz; cz = ncz;
            }
        }
        fp[19] = packh2(carry, 0.f);
#pragma unroll
        for (int c = 0; c < 5; ++c) {
            uint4 H = make_uint4(fp[4 * c + 0], fp[4 * c + 1],
                                 fp[4 * c + 2], fp[4 * c + 3]);
            *(uint4*)(sm + bA + pt * ASTR + half * 80 + c * 16) = H;
        }
    };
    auto stage_b = [&](int p) {
        const int bB = (p & 1) ? SM_B1 : SM_B0;
        const char* src = (const char*)(g_Bh + p * (KP * 72));
        for (int i = tid * 16; i < 11520; i += 256 * 16)
            cpasync16(sb + bB + i, src + i);
        CP_COMMIT();
    };

    float acc[2][4][4];
#pragma unroll
    for (int a = 0; a < 2; ++a)
#pragma unroll
        for (int b = 0; b < 4; ++b)
#pragma unroll
            for (int c = 0; c < 4; ++c) acc[a][b][c] = 0.f;

    stage_b(0);
    do_features(0);
    CP_WAIT0();
    __syncthreads();

    for (int p = 0; p < NPH; ++p) {
        const int bB = (p & 1) ? SM_B1 : SM_B0;
        const int bA = (p & 1) ? SM_A1 : SM_A0;

        if (p + 1 < NPH) stage_b(p + 1);

#pragma unroll
        for (int ks = 0; ks < 5; ++ks) {
            uint32_t ah[2][4];
#pragma unroll
            for (int mt = 0; mt < 2; ++mt) {
                uint32_t ra = (uint32_t)((wr * 32 + mt * 16 + (oct & 1) * 8 + oi) * ASTR
                                         + ks * 32 + (oct >> 1) * 16);
                ldsm4(ah[mt], sb + bA + ra);
            }
#pragma unroll
            for (int np = 0; np < 2; ++np) {
                uint32_t rb = (uint32_t)((ks * 16 + (oct & 1) * 8 + oi) * BSTR
                                         + wc * 64 + np * 32 + (oct >> 1) * 16);
                uint32_t bh[4];
                ldsm4t(bh, sb + bB + rb);
#pragma unroll
                for (int mt = 0; mt < 2; ++mt) {
                    mma16816h(acc[mt][2 * np + 0], ah[mt], bh[0], bh[1]);
                    mma16816h(acc[mt][2 * np + 1], ah[mt], bh[2], bh[3]);
                }
            }
        }

        if (p + 1 < NPH) {
            do_features(p + 1);
            CP_WAIT0();
            __syncthreads();
        }
    }
    __syncthreads();   // mainloop done; A/B regions free

    // ---- Epilogue: layer-2 on tensor cores ----
    // Stage B2 (w1 fp16 hi/lo) into smem
    {
        const uint4* s1 = (const uint4*)g_B2h;
        const uint4* s2 = (const uint4*)g_B2l;
        uint4* d1 = (uint4*)(sm + SM_B2H);
        uint4* d2p = (uint4*)(sm + SM_B2L);
        for (int i = tid; i < 320; i += 256) { d1[i] = s1[i]; d2p[i] = s2[i]; }
    }
    // Store relu(acc) as fp16 hi/lo H tiles (fragment -> row-major [128 x 64])
#pragma unroll
    for (int mt = 0; mt < 2; ++mt)
#pragma unroll
        for (int nt = 0; nt < 4; ++nt) {
            const int cc = wc * 32 + nt * 8 + (lane & 3) * 2;
#pragma unroll
            for (int hr = 0; hr < 2; ++hr) {
                const int rr = wr * 32 + mt * 16 + (lane >> 2) + hr * 8;
                float v0 = fmaxf(acc[mt][nt][2 * hr + 0], 0.f);
                float v1 = fmaxf(acc[mt][nt][2 * hr + 1], 0.f);
                __half h0 = __float2half_rn(v0), h1 = __float2half_rn(v1);
                uint32_t hi = (uint32_t)__half_as_ushort(h0)
                            | ((uint32_t)__half_as_ushort(h1) << 16);
                float r0 = v0 - __half2float(h0), r1 = v1 - __half2float(h1);
                uint32_t lo = (uint32_t)__half_as_ushort(__float2half_rn(r0))
                            | ((uint32_t)__half_as_ushort(__float2half_rn(r1)) << 16);
                *(uint32_t*)(sm + SM_HH + rr * HSTR + cc * 2) = hi;
                *(uint32_t*)(sm + SM_HL + rr * HSTR + cc * 2) = lo;
            }
        }
    __syncthreads();

    // gemm2: D2[128x32] = H[128x64] @ B2[64x32], 3-pass (hh + hl + lh)
    // warp: rows [wr*32,+32), cols [wc*16,+16)
    float d2[2][2][4];
#pragma unroll
    for (int a = 0; a < 2; ++a)
#pragma unroll
        for (int b = 0; b < 2; ++b)
#pragma unroll
            for (int c = 0; c < 4; ++c) d2[a][b][c] = 0.f;

#pragma unroll
    for (int ks = 0; ks < 4; ++ks) {
        uint32_t ah[2][4], al[2][4];
#pragma unroll
        for (int mt = 0; mt < 2; ++mt) {
            uint32_t ra = (uint32_t)((wr * 32 + mt * 16 + (oct & 1) * 8 + oi) * HSTR
                                     + ks * 32 + (oct >> 1) * 16);
            ldsm4(ah[mt], sb + SM_HH + ra);
            ldsm4(al[mt], sb + SM_HL + ra);
        }
        uint32_t rb = (uint32_t)((ks * 16 + (oct & 1) * 8 + oi) * B2STR
                                 + wc * 32 + (oct >> 1) * 16);
        uint32_t bh[4], bl[4];
        ldsm4t(bh, sb + SM_B2H + rb);
        ldsm4t(bl, sb + SM_B2L + rb);
#pragma unroll
        for (int mt = 0; mt < 2; ++mt)
#pragma unroll
            for (int nb = 0; nb < 2; ++nb) {
                mma16816h(d2[mt][nb], ah[mt], bh[2 * nb], bh[2 * nb + 1]);
                mma16816h(d2[mt][nb], ah[mt], bl[2 * nb], bl[2 * nb + 1]);
                mma16816h(d2[mt][nb], al[mt], bh[2 * nb], bh[2 * nb + 1]);
            }
    }

    // sigma = relu(D2) -> g_h row-major [NPTS, NJ] (jj < 24 only)
#pragma unroll
    for (int mt = 0; mt < 2; ++mt)
#pragma unroll
        for (int nb = 0; nb < 2; ++nb) {
            const int jj = wc * 16 + nb * 8 + (lane & 3) * 2;
            if (jj < NJ) {
#pragma unroll
                for (int hr = 0; hr < 2; ++hr) {
                    const int rr = wr * 32 + mt * 16 + (lane >> 2) + hr * 8;
                    float2 v;
                    v.x = fmaxf(d2[mt][nb][2 * hr + 0], 0.f);
                    v.y = fmaxf(d2[mt][nb][2 * hr + 1], 0.f);
                    *(float2*)&g_h[(size_t)(blockIdx.x * 128 + rr) * NJ + jj] = v;
                }
            }
        }
}

// ---------------------------------------------------------------------------
// Kernel 2: scrambled-weight readback + normalized transform blend
// ---------------------------------------------------------------------------
__global__ __launch_bounds__(256)
void warp_kernel(const float* __restrict__ xyz,
                 const float* __restrict__ vdir,
                 const float* __restrict__ transforms,
                 float* __restrict__ out)
{
    __shared__ float str[NJ * 16];
    const int tid = threadIdx.x;
    const int m   = blockIdx.x * 256 + tid;
    for (int i = tid; i < NJ * 16; i += 256) str[i] = transforms[i];
    __syncthreads();

    float w[NJ];
    float s = 0.f;
#pragma unroll
    for (int j = 0; j < NJ; ++j) {
        w[j] = g_h[(size_t)j * NPTS + m];
        s += w[j];
    }
    const float inv = 1.0f / (s + 1e-6f);

    const float x  = xyz[3 * m + 0], y  = xyz[3 * m + 1], z  = xyz[3 * m + 2];
    const float vx = vdir[3 * m + 0], vy = vdir[3 * m + 1], vz = vdir[3 * m + 2];
    const float x2 = x - vx, y2 = y - vy, z2 = z - vz;

    float a1x = 0.f, a1y = 0.f, a1z = 0.f;
    float a2x = 0.f, a2y = 0.f, a2z = 0.f;
#pragma unroll
    for (int j = 0; j < NJ; ++j) {
        const float wn = w[j] * inv;
        const float* T = &str[j * 16];
        a1x = fmaf(wn, fmaf(T[0], x,  fmaf(T[1], y,  fmaf(T[2],  z,  T[3]))),  a1x);
        a1y = fmaf(wn, fmaf(T[4], x,  fmaf(T[5], y,  fmaf(T[6],  z,  T[7]))),  a1y);
        a1z = fmaf(wn, fmaf(T[8], x,  fmaf(T[9], y,  fmaf(T[10], z,  T[11]))), a1z);
        a2x = fmaf(wn, fmaf(T[0], x2, fmaf(T[1], y2, fmaf(T[2],  z2, T[3]))),  a2x);
        a2y = fmaf(wn, fmaf(T[4], x2, fmaf(T[5], y2, fmaf(T[6],  z2, T[7]))),  a2y);
        a2z = fmaf(wn, fmaf(T[8], x2, fmaf(T[9], y2, fmaf(T[10], z2, T[11]))), a2z);
    }

    out[3 * m + 0] = a1x;
    out[3 * m + 1] = a1y;
    out[3 * m + 2] = a1z;
    float* o2 = out + (size_t)3 * NPTS;
    o2[3 * m + 0] = a1x - a2x;
    o2[3 * m + 1] = a1y - a2y;
    o2[3 * m + 2] = a1z - a2z;
}

// ---------------------------------------------------------------------------
// Inputs: xyz_sampled, viewdirs, transforms, ray_valid(unused), w0, w1
// ---------------------------------------------------------------------------
extern "C" void kernel_launch(void* const* d_in, const int* in_sizes, int n_in,
                              void* d_out, int out_size)
{
    const float* xyz = (const float*)d_in[0];
    const float* vd  = (const float*)d_in[1];
    const float* tr  = (const float*)d_in[2];
    const float* w0  = (const float*)d_in[4];
    const float* w1  = (const float*)d_in[5];
    float* out = (float*)d_out;

    // Unconditional every call: deterministic, not a stream op (capture-safe).
    cudaFuncSetAttribute(weights_mma, cudaFuncAttributeMaxDynamicSharedMemorySize, SM_SZ);

    prep_b<<<(NPH * KP * 72 + 64 * 40 + 255) / 256, 256>>>(w0, w1);
    weights_mma<<<NPTS / 128, 256, SM_SZ>>>(xyz, tr);
    warp_kernel<<<NPTS / 256, 256>>>(xyz, vd, tr, out);
}